// round 14
// baseline (speedup 1.0000x reference)
#include <cuda_runtime.h>
#include <cstdint>
#include <cstddef>

// ---------------------------------------------------------------------------
// Selection_window: B=8,K=8,L=4096,D=256,S=1024
//   rows r in [0,65536): bk = r>>10, s = r&1023, source row = 2*s
//   H1 = relu(Xs @ W1 + b1)            (65536 x 512)
//   offset = relu(H1 @ W2 + b2) @ W3   (65536)
//   p = 2*s + offset; linear interp gather from input; mask = (p <= argmax(event_time[b]))
// Output layout: out[65536*256] floats, then mask[65536] floats.
// ---------------------------------------------------------------------------

#define MROWS 65536
#define N1 512
#define K1 256
#define N2 256
#define K2 512
#define OUT_OFF 16777216ULL // MROWS*256

#define BM 128
#define BN 128
#define BKC 16

__device__ float g_H1[(size_t)MROWS * N1];   // 128 MB scratch
__device__ float g_offpart[2 * MROWS];
__device__ float g_limit[8];

// ---- packed f32x2 helpers (sm_103a) ----
__device__ __forceinline__ unsigned long long pack_dup(float a) {
    unsigned long long r;
    unsigned int u = __float_as_uint(a);
    asm("mov.b64 %0, {%1, %1};" : "=l"(r) : "r"(u));
    return r;
}
__device__ __forceinline__ void ffma2(unsigned long long& acc, unsigned long long a,
                                      unsigned long long b) {
    asm("fma.rn.f32x2 %0, %1, %2, %0;" : "+l"(acc) : "l"(a), "l"(b));
}
__device__ __forceinline__ void unpack2(unsigned long long v, float& lo, float& hi) {
    unsigned int a, b;
    asm("mov.b64 {%0, %1}, %2;" : "=r"(a), "=r"(b) : "l"(v));
    lo = __uint_as_float(a);
    hi = __uint_as_float(b);
}

// ---------------------------------------------------------------------------
// argmax(event_time[b], axis=-1) -> float index (first max)
// ---------------------------------------------------------------------------
__global__ void argmax_kernel(const float* __restrict__ et) {
    const int b = blockIdx.x;
    const int tid = threadIdx.x;
    const float* row = et + (size_t)b * 4096;
    float bv = -1.0f;
    int bi = 0;
    for (int i = tid; i < 4096; i += 256) {
        float v = row[i];
        if (v > bv) { bv = v; bi = i; }
    }
    __shared__ float sv[256];
    __shared__ int si[256];
    sv[tid] = bv; si[tid] = bi;
    __syncthreads();
    for (int st = 128; st > 0; st >>= 1) {
        if (tid < st) {
            if (sv[tid + st] > sv[tid] ||
                (sv[tid + st] == sv[tid] && si[tid + st] < si[tid])) {
                sv[tid] = sv[tid + st];
                si[tid] = si[tid + st];
            }
        }
        __syncthreads();
    }
    if (tid == 0) g_limit[b] = (float)si[0];
}

// ---------------------------------------------------------------------------
// GEMM1: g_H1 = relu( gather(input) @ W1 + b1 )
//   A: 65536 x 256 (gathered even rows), B: W1 256 x 512 row-major
//   grid (N1/BN=4, MROWS/BM=512), 256 threads, 8x8 micro-tile via f32x2 pairs
// ---------------------------------------------------------------------------
__global__ __launch_bounds__(256, 2)
void gemm1_kernel(const float* __restrict__ X, const float* __restrict__ W1,
                  const float* __restrict__ b1) {
    __shared__ __align__(16) float As[BKC][BM + 4];
    __shared__ __align__(16) float Bs[BKC][BN];

    const int tid = threadIdx.x;
    const int tx = tid & 15;   // n-group
    const int ty = tid >> 4;   // m-group
    const int bn = blockIdx.x;
    const int bm = blockIdx.y;

    unsigned long long acc[8][4];
#pragma unroll
    for (int i = 0; i < 8; i++)
#pragma unroll
        for (int j = 0; j < 4; j++) acc[i][j] = 0ULL;

    // A loads: rows lm, lm+64 of the 128-row tile; cols lk..lk+3
    const int lm = tid >> 2;
    const int lk = (tid & 3) * 4;
    const int r0 = bm * BM + lm;
    const int r1 = r0 + 64;
    const float* a0p = X + (((size_t)(r0 >> 10) * 4096 + 2 * (r0 & 1023)) * 256) + lk;
    const float* a1p = X + (((size_t)(r1 >> 10) * 4096 + 2 * (r1 & 1023)) * 256) + lk;

    // B loads: rows bkr, bkr+8; cols bnc..bnc+3 of the 128-col block
    const int bkr = tid >> 5;
    const int bnc = (tid & 31) * 4;
    const float* bp = W1 + (size_t)bkr * N1 + bn * BN + bnc;

    for (int kk = 0; kk < K1; kk += BKC) {
        float4 a0 = *(const float4*)(a0p + kk);
        float4 a1 = *(const float4*)(a1p + kk);
        float4 w0 = *(const float4*)(bp + (size_t)kk * N1);
        float4 w1 = *(const float4*)(bp + (size_t)(kk + 8) * N1);

        As[lk + 0][lm] = a0.x; As[lk + 1][lm] = a0.y;
        As[lk + 2][lm] = a0.z; As[lk + 3][lm] = a0.w;
        As[lk + 0][lm + 64] = a1.x; As[lk + 1][lm + 64] = a1.y;
        As[lk + 2][lm + 64] = a1.z; As[lk + 3][lm + 64] = a1.w;
        *(float4*)&Bs[bkr][bnc] = w0;
        *(float4*)&Bs[bkr + 8][bnc] = w1;
        __syncthreads();

#pragma unroll
        for (int k = 0; k < BKC; k++) {
            float4 aA = *(const float4*)&As[k][ty * 8];
            float4 aB = *(const float4*)&As[k][ty * 8 + 4];
            ulonglong2 bA = *(const ulonglong2*)&Bs[k][tx * 8];
            ulonglong2 bB = *(const ulonglong2*)&Bs[k][tx * 8 + 4];
            unsigned long long bb0 = bA.x, bb1 = bA.y, bb2 = bB.x, bb3 = bB.y;
            float av[8] = {aA.x, aA.y, aA.z, aA.w, aB.x, aB.y, aB.z, aB.w};
#pragma unroll
            for (int i = 0; i < 8; i++) {
                unsigned long long ai = pack_dup(av[i]);
                ffma2(acc[i][0], ai, bb0);
                ffma2(acc[i][1], ai, bb1);
                ffma2(acc[i][2], ai, bb2);
                ffma2(acc[i][3], ai, bb3);
            }
        }
        __syncthreads();
    }

    const int n0 = bn * BN + tx * 8;
    float bias[8];
#pragma unroll
    for (int j = 0; j < 8; j++) bias[j] = b1[n0 + j];
#pragma unroll
    for (int i = 0; i < 8; i++) {
        const int r = bm * BM + ty * 8 + i;
        float o[8];
#pragma unroll
        for (int j = 0; j < 4; j++) unpack2(acc[i][j], o[2 * j], o[2 * j + 1]);
        float4 v0, v1;
        v0.x = fmaxf(o[0] + bias[0], 0.f); v0.y = fmaxf(o[1] + bias[1], 0.f);
        v0.z = fmaxf(o[2] + bias[2], 0.f); v0.w = fmaxf(o[3] + bias[3], 0.f);
        v1.x = fmaxf(o[4] + bias[4], 0.f); v1.y = fmaxf(o[5] + bias[5], 0.f);
        v1.z = fmaxf(o[6] + bias[6], 0.f); v1.w = fmaxf(o[7] + bias[7], 0.f);
        *(float4*)(g_H1 + (size_t)r * N1 + n0) = v0;
        *(float4*)(g_H1 + (size_t)r * N1 + n0 + 4) = v1;
    }
}

// ---------------------------------------------------------------------------
// GEMM2 (+fused W3 dot): g_offpart = sum_n relu(H1 @ W2 + b2)[:,n] * W3[n]
//   A: g_H1 65536 x 512, B: W2 512 x 256, grid (2, 512)
// ---------------------------------------------------------------------------
__global__ __launch_bounds__(256, 2)
void gemm2_kernel(const float* __restrict__ W2, const float* __restrict__ b2,
                  const float* __restrict__ W3) {
    __shared__ __align__(16) float As[BKC][BM + 4];
    __shared__ __align__(16) float Bs[BKC][BN];

    const int tid = threadIdx.x;
    const int tx = tid & 15;
    const int ty = tid >> 4;
    const int bn = blockIdx.x; // 0..1
    const int bm = blockIdx.y; // 0..511

    unsigned long long acc[8][4];
#pragma unroll
    for (int i = 0; i < 8; i++)
#pragma unroll
        for (int j = 0; j < 4; j++) acc[i][j] = 0ULL;

    const int lm = tid >> 2;
    const int lk = (tid & 3) * 4;
    const float* a0p = g_H1 + (size_t)(bm * BM + lm) * K2 + lk;
    const float* a1p = g_H1 + (size_t)(bm * BM + lm + 64) * K2 + lk;

    const int bkr = tid >> 5;
    const int bnc = (tid & 31) * 4;
    const float* bp = W2 + (size_t)bkr * N2 + bn * BN + bnc;

    for (int kk = 0; kk < K2; kk += BKC) {
        float4 a0 = *(const float4*)(a0p + kk);
        float4 a1 = *(const float4*)(a1p + kk);
        float4 w0 = *(const float4*)(bp + (size_t)kk * N2);
        float4 w1 = *(const float4*)(bp + (size_t)(kk + 8) * N2);

        As[lk + 0][lm] = a0.x; As[lk + 1][lm] = a0.y;
        As[lk + 2][lm] = a0.z; As[lk + 3][lm] = a0.w;
        As[lk + 0][lm + 64] = a1.x; As[lk + 1][lm + 64] = a1.y;
        As[lk + 2][lm + 64] = a1.z; As[lk + 3][lm + 64] = a1.w;
        *(float4*)&Bs[bkr][bnc] = w0;
        *(float4*)&Bs[bkr + 8][bnc] = w1;
        __syncthreads();

#pragma unroll
        for (int k = 0; k < BKC; k++) {
            float4 aA = *(const float4*)&As[k][ty * 8];
            float4 aB = *(const float4*)&As[k][ty * 8 + 4];
            ulonglong2 bA = *(const ulonglong2*)&Bs[k][tx * 8];
            ulonglong2 bB = *(const ulonglong2*)&Bs[k][tx * 8 + 4];
            unsigned long long bb0 = bA.x, bb1 = bA.y, bb2 = bB.x, bb3 = bB.y;
            float av[8] = {aA.x, aA.y, aA.z, aA.w, aB.x, aB.y, aB.z, aB.w};
#pragma unroll
            for (int i = 0; i < 8; i++) {
                unsigned long long ai = pack_dup(av[i]);
                ffma2(acc[i][0], ai, bb0);
                ffma2(acc[i][1], ai, bb1);
                ffma2(acc[i][2], ai, bb2);
                ffma2(acc[i][3], ai, bb3);
            }
        }
        __syncthreads();
    }

    // epilogue: relu(+b2), dot with W3 across this 128-col block, reduce over tx
    const int n0 = bn * BN + tx * 8;
    float bias[8], w3v[8];
#pragma unroll
    for (int j = 0; j < 8; j++) { bias[j] = b2[n0 + j]; w3v[j] = W3[n0 + j]; }

#pragma unroll
    for (int i = 0; i < 8; i++) {
        float o[8];
#pragma unroll
        for (int j = 0; j < 4; j++) unpack2(acc[i][j], o[2 * j], o[2 * j + 1]);
        float rowsum = 0.f;
#pragma unroll
        for (int j = 0; j < 8; j++) rowsum += fmaxf(o[j] + bias[j], 0.f) * w3v[j];
        // reduce over the 16 tx lanes (xor bits 0..3 stay within tx)
        rowsum += __shfl_xor_sync(0xffffffffu, rowsum, 1);
        rowsum += __shfl_xor_sync(0xffffffffu, rowsum, 2);
        rowsum += __shfl_xor_sync(0xffffffffu, rowsum, 4);
        rowsum += __shfl_xor_sync(0xffffffffu, rowsum, 8);
        if (tx == 0) {
            const int r = bm * BM + ty * 8 + i;
            g_offpart[(size_t)bn * MROWS + r] = rowsum;
        }
    }
}

// ---------------------------------------------------------------------------
// Interp + mask: 4 rows per 256-thread block, 64 lanes x float4 per row
// ---------------------------------------------------------------------------
__global__ void interp_kernel(const float* __restrict__ X, float* __restrict__ out) {
    const int tid = threadIdx.x;
    const int r = blockIdx.x * 4 + (tid >> 6);
    const int lane = tid & 63;

    const int bk = r >> 10;
    const int s = r & 1023;
    const int b = bk >> 3;

    const float off = g_offpart[r] + g_offpart[MROWS + r];
    const float p = 2.0f * (float)s + off;

    if (lane == 0) {
        out[OUT_OFF + (size_t)r] = (p <= g_limit[b]) ? 1.0f : 0.0f;
    }

    const float x0 = floorf(p);
    const float w = p - x0;
    const int i0 = (int)x0;
    const int i1 = i0 + 1;
    const float v0 = (i0 >= 0 && i0 < 4096) ? 1.0f : 0.0f;
    const float v1 = (i1 >= 0 && i1 < 4096) ? 1.0f : 0.0f;
    const int c0 = min(max(i0, 0), 4095);
    const int c1 = min(max(i1, 0), 4095);

    const float4* p0 = (const float4*)(X + ((size_t)bk * 4096 + c0) * 256) + lane;
    const float4* p1 = (const float4*)(X + ((size_t)bk * 4096 + c1) * 256) + lane;
    const float4 a = *p0;
    const float4 c = *p1;
    const float wa = (1.0f - w) * v0;
    const float wb = w * v1;

    float4 o;
    o.x = wa * a.x + wb * c.x;
    o.y = wa * a.y + wb * c.y;
    o.z = wa * a.z + wb * c.z;
    o.w = wa * a.w + wb * c.w;
    *((float4*)(out + (size_t)r * 256) + lane) = o;
}

// ---------------------------------------------------------------------------
extern "C" void kernel_launch(void* const* d_in, const int* in_sizes, int n_in,
                              void* d_out, int out_size) {
    const float* input      = (const float*)d_in[0]; // (8,8,4096,256)
    const float* event_time = (const float*)d_in[1]; // (8,4096)
    const float* W1         = (const float*)d_in[2]; // (256,512)
    const float* b1         = (const float*)d_in[3]; // (512)
    const float* W2         = (const float*)d_in[4]; // (512,256)
    const float* b2         = (const float*)d_in[5]; // (256)
    const float* W3         = (const float*)d_in[6]; // (256,1)
    float* out = (float*)d_out;

    argmax_kernel<<<8, 256>>>(event_time);
    gemm1_kernel<<<dim3(4, 512), 256>>>(input, W1, b1);
    gemm2_kernel<<<dim3(2, 512), 256>>>(W2, b2, W3);
    interp_kernel<<<MROWS / 4, 256>>>(input, out);
}

// round 15
// speedup vs baseline: 1.0020x; 1.0020x over previous
#include <cuda_runtime.h>
#include <cstdint>
#include <cstddef>

// ---------------------------------------------------------------------------
// Selection_window: B=8,K=8,L=4096,D=256,S=1024
//   rows r in [0,65536): bk = r>>10, s = r&1023, source row = 2*s
//   H1 = relu(Xs @ W1 + b1)            (65536 x 512)
//   offset = relu(H1 @ W2 + b2) @ W3   (65536)
//   p = 2*s + offset; linear interp gather from input; mask = (p <= argmax(event_time[b]))
// Output layout: out[65536*256] floats, then mask[65536] floats.
// ---------------------------------------------------------------------------

#define MROWS 65536
#define N1 512
#define K1 256
#define N2 256
#define K2 512
#define OUT_OFF 16777216ULL // MROWS*256

#define BM 128
#define BN 128
#define BKC 16

__device__ float g_H1[(size_t)MROWS * N1];   // 128 MB scratch
__device__ float g_offpart[2 * MROWS];
__device__ float g_limit[8];

// ---- packed f32x2 helpers (sm_103a) ----
__device__ __forceinline__ unsigned long long pack_dup(float a) {
    unsigned long long r;
    unsigned int u = __float_as_uint(a);
    asm("mov.b64 %0, {%1, %1};" : "=l"(r) : "r"(u));
    return r;
}
__device__ __forceinline__ void ffma2(unsigned long long& acc, unsigned long long a,
                                      unsigned long long b) {
    asm("fma.rn.f32x2 %0, %1, %2, %0;" : "+l"(acc) : "l"(a), "l"(b));
}
__device__ __forceinline__ void unpack2(unsigned long long v, float& lo, float& hi) {
    unsigned int a, b;
    asm("mov.b64 {%0, %1}, %2;" : "=r"(a), "=r"(b) : "l"(v));
    lo = __uint_as_float(a);
    hi = __uint_as_float(b);
}

// ---------------------------------------------------------------------------
// argmax(event_time[b], axis=-1) -> float index (first max)
// ---------------------------------------------------------------------------
__global__ void argmax_kernel(const float* __restrict__ et) {
    const int b = blockIdx.x;
    const int tid = threadIdx.x;
    const float* row = et + (size_t)b * 4096;
    float bv = -1.0f;
    int bi = 0;
    for (int i = tid; i < 4096; i += 256) {
        float v = row[i];
        if (v > bv) { bv = v; bi = i; }
    }
    __shared__ float sv[256];
    __shared__ int si[256];
    sv[tid] = bv; si[tid] = bi;
    __syncthreads();
    for (int st = 128; st > 0; st >>= 1) {
        if (tid < st) {
            if (sv[tid + st] > sv[tid] ||
                (sv[tid + st] == sv[tid] && si[tid + st] < si[tid])) {
                sv[tid] = sv[tid + st];
                si[tid] = si[tid + st];
            }
        }
        __syncthreads();
    }
    if (tid == 0) g_limit[b] = (float)si[0];
}

// ---------------------------------------------------------------------------
// GEMM1: g_H1 = relu( gather(input) @ W1 + b1 )
//   A: 65536 x 256 (gathered even rows), B: W1 256 x 512 row-major
//   grid (N1/BN=4, MROWS/BM=512), 256 threads, 8x8 micro-tile via f32x2 pairs
// ---------------------------------------------------------------------------
__global__ __launch_bounds__(256, 2)
void gemm1_kernel(const float* __restrict__ X, const float* __restrict__ W1,
                  const float* __restrict__ b1) {
    __shared__ __align__(16) float As[BKC][BM + 4];
    __shared__ __align__(16) float Bs[BKC][BN];

    const int tid = threadIdx.x;
    const int tx = tid & 15;   // n-group
    const int ty = tid >> 4;   // m-group
    const int bn = blockIdx.x;
    const int bm = blockIdx.y;

    unsigned long long acc[8][4];
#pragma unroll
    for (int i = 0; i < 8; i++)
#pragma unroll
        for (int j = 0; j < 4; j++) acc[i][j] = 0ULL;

    // A loads: rows lm, lm+64 of the 128-row tile; cols lk..lk+3
    const int lm = tid >> 2;
    const int lk = (tid & 3) * 4;
    const int r0 = bm * BM + lm;
    const int r1 = r0 + 64;
    const float* a0p = X + (((size_t)(r0 >> 10) * 4096 + 2 * (r0 & 1023)) * 256) + lk;
    const float* a1p = X + (((size_t)(r1 >> 10) * 4096 + 2 * (r1 & 1023)) * 256) + lk;

    // B loads: rows bkr, bkr+8; cols bnc..bnc+3 of the 128-col block
    const int bkr = tid >> 5;
    const int bnc = (tid & 31) * 4;
    const float* bp = W1 + (size_t)bkr * N1 + bn * BN + bnc;

    for (int kk = 0; kk < K1; kk += BKC) {
        float4 a0 = *(const float4*)(a0p + kk);
        float4 a1 = *(const float4*)(a1p + kk);
        float4 w0 = *(const float4*)(bp + (size_t)kk * N1);
        float4 w1 = *(const float4*)(bp + (size_t)(kk + 8) * N1);

        As[lk + 0][lm] = a0.x; As[lk + 1][lm] = a0.y;
        As[lk + 2][lm] = a0.z; As[lk + 3][lm] = a0.w;
        As[lk + 0][lm + 64] = a1.x; As[lk + 1][lm + 64] = a1.y;
        As[lk + 2][lm + 64] = a1.z; As[lk + 3][lm + 64] = a1.w;
        *(float4*)&Bs[bkr][bnc] = w0;
        *(float4*)&Bs[bkr + 8][bnc] = w1;
        __syncthreads();

#pragma unroll
        for (int k = 0; k < BKC; k++) {
            float4 aA = *(const float4*)&As[k][ty * 8];
            float4 aB = *(const float4*)&As[k][ty * 8 + 4];
            ulonglong2 bA = *(const ulonglong2*)&Bs[k][tx * 8];
            ulonglong2 bB = *(const ulonglong2*)&Bs[k][tx * 8 + 4];
            unsigned long long bb0 = bA.x, bb1 = bA.y, bb2 = bB.x, bb3 = bB.y;
            float av[8] = {aA.x, aA.y, aA.z, aA.w, aB.x, aB.y, aB.z, aB.w};
#pragma unroll
            for (int i = 0; i < 8; i++) {
                unsigned long long ai = pack_dup(av[i]);
                ffma2(acc[i][0], ai, bb0);
                ffma2(acc[i][1], ai, bb1);
                ffma2(acc[i][2], ai, bb2);
                ffma2(acc[i][3], ai, bb3);
            }
        }
        __syncthreads();
    }

    const int n0 = bn * BN + tx * 8;
    float bias[8];
#pragma unroll
    for (int j = 0; j < 8; j++) bias[j] = b1[n0 + j];
#pragma unroll
    for (int i = 0; i < 8; i++) {
        const int r = bm * BM + ty * 8 + i;
        float o[8];
#pragma unroll
        for (int j = 0; j < 4; j++) unpack2(acc[i][j], o[2 * j], o[2 * j + 1]);
        float4 v0, v1;
        v0.x = fmaxf(o[0] + bias[0], 0.f); v0.y = fmaxf(o[1] + bias[1], 0.f);
        v0.z = fmaxf(o[2] + bias[2], 0.f); v0.w = fmaxf(o[3] + bias[3], 0.f);
        v1.x = fmaxf(o[4] + bias[4], 0.f); v1.y = fmaxf(o[5] + bias[5], 0.f);
        v1.z = fmaxf(o[6] + bias[6], 0.f); v1.w = fmaxf(o[7] + bias[7], 0.f);
        *(float4*)(g_H1 + (size_t)r * N1 + n0) = v0;
        *(float4*)(g_H1 + (size_t)r * N1 + n0 + 4) = v1;
    }
}

// ---------------------------------------------------------------------------
// GEMM2 (+fused W3 dot): g_offpart = sum_n relu(H1 @ W2 + b2)[:,n] * W3[n]
//   A: g_H1 65536 x 512, B: W2 512 x 256, grid (2, 512)
// ---------------------------------------------------------------------------
__global__ __launch_bounds__(256, 2)
void gemm2_kernel(const float* __restrict__ W2, const float* __restrict__ b2,
                  const float* __restrict__ W3) {
    __shared__ __align__(16) float As[BKC][BM + 4];
    __shared__ __align__(16) float Bs[BKC][BN];

    const int tid = threadIdx.x;
    const int tx = tid & 15;
    const int ty = tid >> 4;
    const int bn = blockIdx.x; // 0..1
    const int bm = blockIdx.y; // 0..511

    unsigned long long acc[8][4];
#pragma unroll
    for (int i = 0; i < 8; i++)
#pragma unroll
        for (int j = 0; j < 4; j++) acc[i][j] = 0ULL;

    const int lm = tid >> 2;
    const int lk = (tid & 3) * 4;
    const float* a0p = g_H1 + (size_t)(bm * BM + lm) * K2 + lk;
    const float* a1p = g_H1 + (size_t)(bm * BM + lm + 64) * K2 + lk;

    const int bkr = tid >> 5;
    const int bnc = (tid & 31) * 4;
    const float* bp = W2 + (size_t)bkr * N2 + bn * BN + bnc;

    for (int kk = 0; kk < K2; kk += BKC) {
        float4 a0 = *(const float4*)(a0p + kk);
        float4 a1 = *(const float4*)(a1p + kk);
        float4 w0 = *(const float4*)(bp + (size_t)kk * N2);
        float4 w1 = *(const float4*)(bp + (size_t)(kk + 8) * N2);

        As[lk + 0][lm] = a0.x; As[lk + 1][lm] = a0.y;
        As[lk + 2][lm] = a0.z; As[lk + 3][lm] = a0.w;
        As[lk + 0][lm + 64] = a1.x; As[lk + 1][lm + 64] = a1.y;
        As[lk + 2][lm + 64] = a1.z; As[lk + 3][lm + 64] = a1.w;
        *(float4*)&Bs[bkr][bnc] = w0;
        *(float4*)&Bs[bkr + 8][bnc] = w1;
        __syncthreads();

#pragma unroll
        for (int k = 0; k < BKC; k++) {
            float4 aA = *(const float4*)&As[k][ty * 8];
            float4 aB = *(const float4*)&As[k][ty * 8 + 4];
            ulonglong2 bA = *(const ulonglong2*)&Bs[k][tx * 8];
            ulonglong2 bB = *(const ulonglong2*)&Bs[k][tx * 8 + 4];
            unsigned long long bb0 = bA.x, bb1 = bA.y, bb2 = bB.x, bb3 = bB.y;
            float av[8] = {aA.x, aA.y, aA.z, aA.w, aB.x, aB.y, aB.z, aB.w};
#pragma unroll
            for (int i = 0; i < 8; i++) {
                unsigned long long ai = pack_dup(av[i]);
                ffma2(acc[i][0], ai, bb0);
                ffma2(acc[i][1], ai, bb1);
                ffma2(acc[i][2], ai, bb2);
                ffma2(acc[i][3], ai, bb3);
            }
        }
        __syncthreads();
    }

    // epilogue: relu(+b2), dot with W3 across this 128-col block, reduce over tx
    const int n0 = bn * BN + tx * 8;
    float bias[8], w3v[8];
#pragma unroll
    for (int j = 0; j < 8; j++) { bias[j] = b2[n0 + j]; w3v[j] = W3[n0 + j]; }

#pragma unroll
    for (int i = 0; i < 8; i++) {
        float o[8];
#pragma unroll
        for (int j = 0; j < 4; j++) unpack2(acc[i][j], o[2 * j], o[2 * j + 1]);
        float rowsum = 0.f;
#pragma unroll
        for (int j = 0; j < 8; j++) rowsum += fmaxf(o[j] + bias[j], 0.f) * w3v[j];
        // reduce over the 16 tx lanes (xor bits 0..3 stay within tx)
        rowsum += __shfl_xor_sync(0xffffffffu, rowsum, 1);
        rowsum += __shfl_xor_sync(0xffffffffu, rowsum, 2);
        rowsum += __shfl_xor_sync(0xffffffffu, rowsum, 4);
        rowsum += __shfl_xor_sync(0xffffffffu, rowsum, 8);
        if (tx == 0) {
            const int r = bm * BM + ty * 8 + i;
            g_offpart[(size_t)bn * MROWS + r] = rowsum;
        }
    }
}

// ---------------------------------------------------------------------------
// Interp + mask: 4 rows per 256-thread block, 64 lanes x float4 per row
// ---------------------------------------------------------------------------
__global__ void interp_kernel(const float* __restrict__ X, float* __restrict__ out) {
    const int tid = threadIdx.x;
    const int r = blockIdx.x * 4 + (tid >> 6);
    const int lane = tid & 63;

    const int bk = r >> 10;
    const int s = r & 1023;
    const int b = bk >> 3;

    const float off = g_offpart[r] + g_offpart[MROWS + r];
    const float p = 2.0f * (float)s + off;

    if (lane == 0) {
        out[OUT_OFF + (size_t)r] = (p <= g_limit[b]) ? 1.0f : 0.0f;
    }

    const float x0 = floorf(p);
    const float w = p - x0;
    const int i0 = (int)x0;
    const int i1 = i0 + 1;
    const float v0 = (i0 >= 0 && i0 < 4096) ? 1.0f : 0.0f;
    const float v1 = (i1 >= 0 && i1 < 4096) ? 1.0f : 0.0f;
    const int c0 = min(max(i0, 0), 4095);
    const int c1 = min(max(i1, 0), 4095);

    const float4* p0 = (const float4*)(X + ((size_t)bk * 4096 + c0) * 256) + lane;
    const float4* p1 = (const float4*)(X + ((size_t)bk * 4096 + c1) * 256) + lane;
    const float4 a = *p0;
    const float4 c = *p1;
    const float wa = (1.0f - w) * v0;
    const float wb = w * v1;

    float4 o;
    o.x = wa * a.x + wb * c.x;
    o.y = wa * a.y + wb * c.y;
    o.z = wa * a.z + wb * c.z;
    o.w = wa * a.w + wb * c.w;
    *((float4*)(out + (size_t)r * 256) + lane) = o;
}

// ---------------------------------------------------------------------------
extern "C" void kernel_launch(void* const* d_in, const int* in_sizes, int n_in,
                              void* d_out, int out_size) {
    const float* input      = (const float*)d_in[0]; // (8,8,4096,256)
    const float* event_time = (const float*)d_in[1]; // (8,4096)
    const float* W1         = (const float*)d_in[2]; // (256,512)
    const float* b1         = (const float*)d_in[3]; // (512)
    const float* W2         = (const float*)d_in[4]; // (512,256)
    const float* b2         = (const float*)d_in[5]; // (256)
    const float* W3         = (const float*)d_in[6]; // (256,1)
    float* out = (float*)d_out;

    argmax_kernel<<<8, 256>>>(event_time);
    gemm1_kernel<<<dim3(4, 512), 256>>>(input, W1, b1);
    gemm2_kernel<<<dim3(2, 512), 256>>>(W2, b2, W3);
    interp_kernel<<<MROWS / 4, 256>>>(input, out);
}

// round 16
// speedup vs baseline: 1.0052x; 1.0032x over previous
#include <cuda_runtime.h>
#include <cstdint>
#include <cstddef>

// ---------------------------------------------------------------------------
// Selection_window: B=8,K=8,L=4096,D=256,S=1024
//   rows r in [0,65536): bk = r>>10, s = r&1023, source row = 2*s
//   H1 = relu(Xs @ W1 + b1)            (65536 x 512)
//   offset = relu(H1 @ W2 + b2) @ W3   (65536)
//   p = 2*s + offset; linear interp gather from input; mask = (p <= argmax(event_time[b]))
// Output layout: out[65536*256] floats, then mask[65536] floats.
// ---------------------------------------------------------------------------

#define MROWS 65536
#define N1 512
#define K1 256
#define N2 256
#define K2 512
#define OUT_OFF 16777216ULL // MROWS*256

#define BM 128
#define BN 128
#define BKC 16

__device__ float g_H1[(size_t)MROWS * N1];   // 128 MB scratch
__device__ float g_offpart[2 * MROWS];
__device__ float g_limit[8];

// ---- packed f32x2 helpers (sm_103a) ----
__device__ __forceinline__ unsigned long long pack_dup(float a) {
    unsigned long long r;
    unsigned int u = __float_as_uint(a);
    asm("mov.b64 %0, {%1, %1};" : "=l"(r) : "r"(u));
    return r;
}
__device__ __forceinline__ void ffma2(unsigned long long& acc, unsigned long long a,
                                      unsigned long long b) {
    asm("fma.rn.f32x2 %0, %1, %2, %0;" : "+l"(acc) : "l"(a), "l"(b));
}
__device__ __forceinline__ void unpack2(unsigned long long v, float& lo, float& hi) {
    unsigned int a, b;
    asm("mov.b64 {%0, %1}, %2;" : "=r"(a), "=r"(b) : "l"(v));
    lo = __uint_as_float(a);
    hi = __uint_as_float(b);
}

// ---------------------------------------------------------------------------
// argmax(event_time[b], axis=-1) -> float index (first max)
// ---------------------------------------------------------------------------
__global__ void argmax_kernel(const float* __restrict__ et) {
    const int b = blockIdx.x;
    const int tid = threadIdx.x;
    const float* row = et + (size_t)b * 4096;
    float bv = -1.0f;
    int bi = 0;
    for (int i = tid; i < 4096; i += 256) {
        float v = row[i];
        if (v > bv) { bv = v; bi = i; }
    }
    __shared__ float sv[256];
    __shared__ int si[256];
    sv[tid] = bv; si[tid] = bi;
    __syncthreads();
    for (int st = 128; st > 0; st >>= 1) {
        if (tid < st) {
            if (sv[tid + st] > sv[tid] ||
                (sv[tid + st] == sv[tid] && si[tid + st] < si[tid])) {
                sv[tid] = sv[tid + st];
                si[tid] = si[tid + st];
            }
        }
        __syncthreads();
    }
    if (tid == 0) g_limit[b] = (float)si[0];
}

// ---------------------------------------------------------------------------
// GEMM1: g_H1 = relu( gather(input) @ W1 + b1 )
//   A: 65536 x 256 (gathered even rows), B: W1 256 x 512 row-major
//   grid (N1/BN=4, MROWS/BM=512), 256 threads, 8x8 micro-tile via f32x2 pairs
// ---------------------------------------------------------------------------
__global__ __launch_bounds__(256, 2)
void gemm1_kernel(const float* __restrict__ X, const float* __restrict__ W1,
                  const float* __restrict__ b1) {
    __shared__ __align__(16) float As[BKC][BM + 4];
    __shared__ __align__(16) float Bs[BKC][BN];

    const int tid = threadIdx.x;
    const int tx = tid & 15;   // n-group
    const int ty = tid >> 4;   // m-group
    const int bn = blockIdx.x;
    const int bm = blockIdx.y;

    unsigned long long acc[8][4];
#pragma unroll
    for (int i = 0; i < 8; i++)
#pragma unroll
        for (int j = 0; j < 4; j++) acc[i][j] = 0ULL;

    // A loads: rows lm, lm+64 of the 128-row tile; cols lk..lk+3
    const int lm = tid >> 2;
    const int lk = (tid & 3) * 4;
    const int r0 = bm * BM + lm;
    const int r1 = r0 + 64;
    const float* a0p = X + (((size_t)(r0 >> 10) * 4096 + 2 * (r0 & 1023)) * 256) + lk;
    const float* a1p = X + (((size_t)(r1 >> 10) * 4096 + 2 * (r1 & 1023)) * 256) + lk;

    // B loads: rows bkr, bkr+8; cols bnc..bnc+3 of the 128-col block
    const int bkr = tid >> 5;
    const int bnc = (tid & 31) * 4;
    const float* bp = W1 + (size_t)bkr * N1 + bn * BN + bnc;

    for (int kk = 0; kk < K1; kk += BKC) {
        float4 a0 = *(const float4*)(a0p + kk);
        float4 a1 = *(const float4*)(a1p + kk);
        float4 w0 = *(const float4*)(bp + (size_t)kk * N1);
        float4 w1 = *(const float4*)(bp + (size_t)(kk + 8) * N1);

        As[lk + 0][lm] = a0.x; As[lk + 1][lm] = a0.y;
        As[lk + 2][lm] = a0.z; As[lk + 3][lm] = a0.w;
        As[lk + 0][lm + 64] = a1.x; As[lk + 1][lm + 64] = a1.y;
        As[lk + 2][lm + 64] = a1.z; As[lk + 3][lm + 64] = a1.w;
        *(float4*)&Bs[bkr][bnc] = w0;
        *(float4*)&Bs[bkr + 8][bnc] = w1;
        __syncthreads();

#pragma unroll
        for (int k = 0; k < BKC; k++) {
            float4 aA = *(const float4*)&As[k][ty * 8];
            float4 aB = *(const float4*)&As[k][ty * 8 + 4];
            ulonglong2 bA = *(const ulonglong2*)&Bs[k][tx * 8];
            ulonglong2 bB = *(const ulonglong2*)&Bs[k][tx * 8 + 4];
            unsigned long long bb0 = bA.x, bb1 = bA.y, bb2 = bB.x, bb3 = bB.y;
            float av[8] = {aA.x, aA.y, aA.z, aA.w, aB.x, aB.y, aB.z, aB.w};
#pragma unroll
            for (int i = 0; i < 8; i++) {
                unsigned long long ai = pack_dup(av[i]);
                ffma2(acc[i][0], ai, bb0);
                ffma2(acc[i][1], ai, bb1);
                ffma2(acc[i][2], ai, bb2);
                ffma2(acc[i][3], ai, bb3);
            }
        }
        __syncthreads();
    }

    const int n0 = bn * BN + tx * 8;
    float bias[8];
#pragma unroll
    for (int j = 0; j < 8; j++) bias[j] = b1[n0 + j];
#pragma unroll
    for (int i = 0; i < 8; i++) {
        const int r = bm * BM + ty * 8 + i;
        float o[8];
#pragma unroll
        for (int j = 0; j < 4; j++) unpack2(acc[i][j], o[2 * j], o[2 * j + 1]);
        float4 v0, v1;
        v0.x = fmaxf(o[0] + bias[0], 0.f); v0.y = fmaxf(o[1] + bias[1], 0.f);
        v0.z = fmaxf(o[2] + bias[2], 0.f); v0.w = fmaxf(o[3] + bias[3], 0.f);
        v1.x = fmaxf(o[4] + bias[4], 0.f); v1.y = fmaxf(o[5] + bias[5], 0.f);
        v1.z = fmaxf(o[6] + bias[6], 0.f); v1.w = fmaxf(o[7] + bias[7], 0.f);
        *(float4*)(g_H1 + (size_t)r * N1 + n0) = v0;
        *(float4*)(g_H1 + (size_t)r * N1 + n0 + 4) = v1;
    }
}

// ---------------------------------------------------------------------------
// GEMM2 (+fused W3 dot): g_offpart = sum_n relu(H1 @ W2 + b2)[:,n] * W3[n]
//   A: g_H1 65536 x 512, B: W2 512 x 256, grid (2, 512)
// ---------------------------------------------------------------------------
__global__ __launch_bounds__(256, 2)
void gemm2_kernel(const float* __restrict__ W2, const float* __restrict__ b2,
                  const float* __restrict__ W3) {
    __shared__ __align__(16) float As[BKC][BM + 4];
    __shared__ __align__(16) float Bs[BKC][BN];

    const int tid = threadIdx.x;
    const int tx = tid & 15;
    const int ty = tid >> 4;
    const int bn = blockIdx.x; // 0..1
    const int bm = blockIdx.y; // 0..511

    unsigned long long acc[8][4];
#pragma unroll
    for (int i = 0; i < 8; i++)
#pragma unroll
        for (int j = 0; j < 4; j++) acc[i][j] = 0ULL;

    const int lm = tid >> 2;
    const int lk = (tid & 3) * 4;
    const float* a0p = g_H1 + (size_t)(bm * BM + lm) * K2 + lk;
    const float* a1p = g_H1 + (size_t)(bm * BM + lm + 64) * K2 + lk;

    const int bkr = tid >> 5;
    const int bnc = (tid & 31) * 4;
    const float* bp = W2 + (size_t)bkr * N2 + bn * BN + bnc;

    for (int kk = 0; kk < K2; kk += BKC) {
        float4 a0 = *(const float4*)(a0p + kk);
        float4 a1 = *(const float4*)(a1p + kk);
        float4 w0 = *(const float4*)(bp + (size_t)kk * N2);
        float4 w1 = *(const float4*)(bp + (size_t)(kk + 8) * N2);

        As[lk + 0][lm] = a0.x; As[lk + 1][lm] = a0.y;
        As[lk + 2][lm] = a0.z; As[lk + 3][lm] = a0.w;
        As[lk + 0][lm + 64] = a1.x; As[lk + 1][lm + 64] = a1.y;
        As[lk + 2][lm + 64] = a1.z; As[lk + 3][lm + 64] = a1.w;
        *(float4*)&Bs[bkr][bnc] = w0;
        *(float4*)&Bs[bkr + 8][bnc] = w1;
        __syncthreads();

#pragma unroll
        for (int k = 0; k < BKC; k++) {
            float4 aA = *(const float4*)&As[k][ty * 8];
            float4 aB = *(const float4*)&As[k][ty * 8 + 4];
            ulonglong2 bA = *(const ulonglong2*)&Bs[k][tx * 8];
            ulonglong2 bB = *(const ulonglong2*)&Bs[k][tx * 8 + 4];
            unsigned long long bb0 = bA.x, bb1 = bA.y, bb2 = bB.x, bb3 = bB.y;
            float av[8] = {aA.x, aA.y, aA.z, aA.w, aB.x, aB.y, aB.z, aB.w};
#pragma unroll
            for (int i = 0; i < 8; i++) {
                unsigned long long ai = pack_dup(av[i]);
                ffma2(acc[i][0], ai, bb0);
                ffma2(acc[i][1], ai, bb1);
                ffma2(acc[i][2], ai, bb2);
                ffma2(acc[i][3], ai, bb3);
            }
        }
        __syncthreads();
    }

    // epilogue: relu(+b2), dot with W3 across this 128-col block, reduce over tx
    const int n0 = bn * BN + tx * 8;
    float bias[8], w3v[8];
#pragma unroll
    for (int j = 0; j < 8; j++) { bias[j] = b2[n0 + j]; w3v[j] = W3[n0 + j]; }

#pragma unroll
    for (int i = 0; i < 8; i++) {
        float o[8];
#pragma unroll
        for (int j = 0; j < 4; j++) unpack2(acc[i][j], o[2 * j], o[2 * j + 1]);
        float rowsum = 0.f;
#pragma unroll
        for (int j = 0; j < 8; j++) rowsum += fmaxf(o[j] + bias[j], 0.f) * w3v[j];
        // reduce over the 16 tx lanes (xor bits 0..3 stay within tx)
        rowsum += __shfl_xor_sync(0xffffffffu, rowsum, 1);
        rowsum += __shfl_xor_sync(0xffffffffu, rowsum, 2);
        rowsum += __shfl_xor_sync(0xffffffffu, rowsum, 4);
        rowsum += __shfl_xor_sync(0xffffffffu, rowsum, 8);
        if (tx == 0) {
            const int r = bm * BM + ty * 8 + i;
            g_offpart[(size_t)bn * MROWS + r] = rowsum;
        }
    }
}

// ---------------------------------------------------------------------------
// Interp + mask: 4 rows per 256-thread block, 64 lanes x float4 per row
// ---------------------------------------------------------------------------
__global__ void interp_kernel(const float* __restrict__ X, float* __restrict__ out) {
    const int tid = threadIdx.x;
    const int r = blockIdx.x * 4 + (tid >> 6);
    const int lane = tid & 63;

    const int bk = r >> 10;
    const int s = r & 1023;
    const int b = bk >> 3;

    const float off = g_offpart[r] + g_offpart[MROWS + r];
    const float p = 2.0f * (float)s + off;

    if (lane == 0) {
        out[OUT_OFF + (size_t)r] = (p <= g_limit[b]) ? 1.0f : 0.0f;
    }

    const float x0 = floorf(p);
    const float w = p - x0;
    const int i0 = (int)x0;
    const int i1 = i0 + 1;
    const float v0 = (i0 >= 0 && i0 < 4096) ? 1.0f : 0.0f;
    const float v1 = (i1 >= 0 && i1 < 4096) ? 1.0f : 0.0f;
    const int c0 = min(max(i0, 0), 4095);
    const int c1 = min(max(i1, 0), 4095);

    const float4* p0 = (const float4*)(X + ((size_t)bk * 4096 + c0) * 256) + lane;
    const float4* p1 = (const float4*)(X + ((size_t)bk * 4096 + c1) * 256) + lane;
    const float4 a = *p0;
    const float4 c = *p1;
    const float wa = (1.0f - w) * v0;
    const float wb = w * v1;

    float4 o;
    o.x = wa * a.x + wb * c.x;
    o.y = wa * a.y + wb * c.y;
    o.z = wa * a.z + wb * c.z;
    o.w = wa * a.w + wb * c.w;
    *((float4*)(out + (size_t)r * 256) + lane) = o;
}

// ---------------------------------------------------------------------------
extern "C" void kernel_launch(void* const* d_in, const int* in_sizes, int n_in,
                              void* d_out, int out_size) {
    const float* input      = (const float*)d_in[0]; // (8,8,4096,256)
    const float* event_time = (const float*)d_in[1]; // (8,4096)
    const float* W1         = (const float*)d_in[2]; // (256,512)
    const float* b1         = (const float*)d_in[3]; // (512)
    const float* W2         = (const float*)d_in[4]; // (512,256)
    const float* b2         = (const float*)d_in[5]; // (256)
    const float* W3         = (const float*)d_in[6]; // (256,1)
    float* out = (float*)d_out;

    argmax_kernel<<<8, 256>>>(event_time);
    gemm1_kernel<<<dim3(4, 512), 256>>>(input, W1, b1);
    gemm2_kernel<<<dim3(2, 512), 256>>>(W2, b2, W3);
    interp_kernel<<<MROWS / 4, 256>>>(input, out);
}